// round 1
// baseline (speedup 1.0000x reference)
#include <cuda_runtime.h>
#include <math.h>

// RRoIAlign: features (8,32,160,160) f32, rois (1024,6) f32 -> out (1024,32,8,64) f32
// One block per ROI (1024 blocks x 256 threads). Each thread owns 2 adjacent bins:
// geometry (offsets + masked bilinear weights) computed once in registers,
// then the channel loop does 8 gathers + blend + one float2 coalesced store.

namespace {

constexpr int PH = 8;
constexpr int PW = 64;
constexpr int CC = 32;
constexpr int HH = 160;
constexpr int WW = 160;
constexpr int NBINS = PH * PW;          // 512
constexpr float SCALE = 0.25f;

__global__ __launch_bounds__(256) void rroi_align_kernel(
    const float* __restrict__ features,
    const float* __restrict__ rois,
    float* __restrict__ out)
{
    const int n   = blockIdx.x;
    const int tid = threadIdx.x;

    // roi row: 6 floats, 8B-aligned (6*4=24B stride) -> three float2 loads
    const float2* rp = reinterpret_cast<const float2*>(rois + (size_t)n * 6);
    const float2 ra = __ldg(rp + 0);   // batch_idx, cx
    const float2 rb = __ldg(rp + 1);   // cy, h
    const float2 rc = __ldg(rp + 2);   // w, ang

    const int   bidx = (int)ra.x;
    const float cx = ra.y, cy = rb.x, hh = rb.y, ww = rc.x, ang = rc.y;

    const float theta = ang * 0.017453292519943295f;  // pi/180
    float sa, ca;
    sincosf(theta, &sa, &ca);

    const float Sx = ww * SCALE / (float)PW;
    const float Sy = hh * SCALE / (float)PH;
    const float dx = -(float)PW * 0.5f;
    const float dy = -(float)PH * 0.5f;
    const float Dx = cx * SCALE;
    const float Dy = cy * SCALE;

    const float M00 = ca * Sx;
    const float M01 = sa * Sy;
    const float M02 = M00 * dx + M01 * dy + Dx;
    const float M10 = -sa * Sx;
    const float M11 = ca * Sy;
    const float M12 = M10 * dx + M11 * dy + Dy;

    int   offs[2][4];
    float wts[2][4];

#pragma unroll
    for (int k = 0; k < 2; k++) {
        const int bin = 2 * tid + k;
        const float pw  = (float)(bin & (PW - 1));
        const float ph  = (float)(bin >> 6);
        const float pw1 = pw + 1.0f;
        const float ph1 = ph + 1.0f;

        const float X0 = M00 * pw  + M01 * ph  + M02;
        const float X1 = M00 * pw  + M01 * ph1 + M02;
        const float X2 = M00 * pw1 + M01 * ph  + M02;
        const float X3 = M00 * pw1 + M01 * ph1 + M02;
        const float Y0 = M10 * pw  + M11 * ph  + M12;
        const float Y1 = M10 * pw  + M11 * ph1 + M12;
        const float Y2 = M10 * pw1 + M11 * ph  + M12;
        const float Y3 = M10 * pw1 + M11 * ph1 + M12;

        const float xmn = fminf(fminf(X0, X1), fminf(X2, X3));
        const float xmx = fmaxf(fmaxf(X0, X1), fmaxf(X2, X3));
        const float ymn = fminf(fminf(Y0, Y1), fminf(Y2, Y3));
        const float ymx = fmaxf(fmaxf(Y0, Y1), fmaxf(Y2, Y3));

        // _round(x) = floor(x + 0.5)
        const float left   = fmaxf(floorf(xmn + 0.5f), 0.0f);
        const float right  = fminf(floorf(xmx + 0.5f), (float)(WW - 1));
        const float top    = fmaxf(floorf(ymn + 0.5f), 0.0f);
        const float bottom = fminf(floorf(ymx + 0.5f), (float)(HH - 1));

        const float bcx = (left + right) * 0.5f;
        const float bcy = (top + bottom) * 0.5f;

        const float bl = floorf(bcx);
        const float br = ceilf(bcx);
        const float bt = floorf(bcy);
        const float bb = ceilf(bcy);
        const float rx = bcx - bl;
        const float ry = bcy - bt;

        const bool vl = (bl > -1.0f) && (bl < (float)WW);
        const bool vr = (br > -1.0f) && (br < (float)WW);
        const bool vt = (bt > -1.0f) && (bt < (float)HH);
        const bool vb = (bb > -1.0f) && (bb < (float)HH);

        float wlt = (1.0f - rx) * (1.0f - ry);
        float wrt = rx * (1.0f - ry);
        float wlb = (1.0f - rx) * ry;
        float wrb = rx * ry;
        if (!(vt && vl)) wlt = 0.0f;
        if (!(vt && vr)) wrt = 0.0f;
        if (!(vb && vl)) wlb = 0.0f;
        if (!(vb && vr)) wrb = 0.0f;

        const int xl = (int)fminf(fmaxf(bl, 0.0f), (float)(WW - 1));
        const int xr = (int)fminf(fmaxf(br, 0.0f), (float)(WW - 1));
        const int yt = (int)fminf(fmaxf(bt, 0.0f), (float)(HH - 1));
        const int yb = (int)fminf(fmaxf(bb, 0.0f), (float)(HH - 1));

        offs[k][0] = yt * WW + xl;  wts[k][0] = wlt;
        offs[k][1] = yt * WW + xr;  wts[k][1] = wrt;
        offs[k][2] = yb * WW + xl;  wts[k][2] = wlb;
        offs[k][3] = yb * WW + xr;  wts[k][3] = wrb;
    }

    const float* fb = features + (size_t)bidx * (CC * HH * WW);
    float* ob = out + (size_t)n * (CC * NBINS) + 2 * tid;

#pragma unroll 4
    for (int c = 0; c < CC; c++) {
        const float* f = fb + c * (HH * WW);
        const float r0 = wts[0][0] * __ldg(f + offs[0][0])
                       + wts[0][1] * __ldg(f + offs[0][1])
                       + wts[0][2] * __ldg(f + offs[0][2])
                       + wts[0][3] * __ldg(f + offs[0][3]);
        const float r1 = wts[1][0] * __ldg(f + offs[1][0])
                       + wts[1][1] * __ldg(f + offs[1][1])
                       + wts[1][2] * __ldg(f + offs[1][2])
                       + wts[1][3] * __ldg(f + offs[1][3]);
        *reinterpret_cast<float2*>(ob + (size_t)c * NBINS) = make_float2(r0, r1);
    }
}

}  // namespace

extern "C" void kernel_launch(void* const* d_in, const int* in_sizes, int n_in,
                              void* d_out, int out_size) {
    const float* features = (const float*)d_in[0];
    const float* rois     = (const float*)d_in[1];
    float* out            = (float*)d_out;

    const int N = in_sizes[1] / 6;  // 1024
    rroi_align_kernel<<<N, 256>>>(features, rois, out);
}

// round 2
// speedup vs baseline: 1.8202x; 1.8202x over previous
#include <cuda_runtime.h>
#include <math.h>

// RRoIAlign, two-kernel plan:
//   K1: transpose features (8,32,160,160) -> NHWC scratch (8,160,160,32), guard-banded.
//   K2: per (roi, ph-row) block: 64 threads compute bin geometry (2x2 patch base +
//       masked bilinear weights) into smem; 512 threads gather float4 channel chunks
//       (all LDG.128 coalesced), blend, transpose through smem, store coalesced.

namespace {

constexpr int PH = 8;
constexpr int PW = 64;
constexpr int CC = 32;
constexpr int HH = 160;
constexpr int WW = 160;
constexpr int BB = 8;
constexpr float SCALE = 0.25f;

constexpr int IMG   = HH * WW * CC;          // floats per batch image (819200)
constexpr int ROWF  = WW * CC;               // floats per pixel-row (5120)
constexpr int GUARD = 524288;                // 2MB guard each side (zero-init)

__device__ float g_nhwc[GUARD + (size_t)BB * IMG + GUARD];

// ---------------- K1: NCHW -> NHWC transpose ----------------
__global__ __launch_bounds__(256) void transpose_kernel(const float* __restrict__ feat)
{
    __shared__ float tile[HH * 33];          // 160 x 32 padded to 33
    const int b = blockIdx.x / HH;
    const int y = blockIdx.x - b * HH;

    const float* src = feat + (size_t)b * IMG + (size_t)y * WW;  // + c*25600 + x
#pragma unroll
    for (int e = threadIdx.x; e < WW * CC; e += 256) {
        const int c = e / WW;                // consecutive tid -> consecutive x
        const int x = e - c * WW;
        tile[x * 33 + c] = __ldg(src + (size_t)c * (HH * WW) + x);
    }
    __syncthreads();

    float* dst = g_nhwc + GUARD + (size_t)b * IMG + (size_t)y * ROWF;
#pragma unroll
    for (int e = threadIdx.x; e < WW * CC; e += 256) {
        const int x = e >> 5;
        const int c = e & 31;
        dst[e] = tile[x * 33 + c];           // coalesced write, conflict-free read
    }
}

// ---------------- K2: gather + blend ----------------
__global__ __launch_bounds__(512, 3) void rroi_gather_kernel(
    const float* __restrict__ rois,
    float* __restrict__ out)
{
    __shared__ int   s_base[PW];
    __shared__ float s_w0[PW], s_w1[PW], s_w2[PW], s_w3[PW];
    __shared__ float s_r[CC * 65];           // 32 channels x 64 bins, padded

    const int n    = blockIdx.x;
    const int ph_i = blockIdx.y;
    const int tid  = threadIdx.x;

    if (tid < PW) {
        const float2* rp = reinterpret_cast<const float2*>(rois + (size_t)n * 6);
        const float2 ra = __ldg(rp + 0);     // batch_idx, cx
        const float2 rb = __ldg(rp + 1);     // cy, h
        const float2 rc = __ldg(rp + 2);     // w, ang

        const int   bidx = (int)ra.x;
        const float cx = ra.y, cy = rb.x, hh = rb.y, ww = rc.x, ang = rc.y;

        const float theta = ang * 0.017453292519943295f;
        float sa, ca;
        sincosf(theta, &sa, &ca);

        const float Sx = ww * SCALE / (float)PW;
        const float Sy = hh * SCALE / (float)PH;
        const float dxc = -(float)PW * 0.5f;
        const float dyc = -(float)PH * 0.5f;
        const float Dx = cx * SCALE;
        const float Dy = cy * SCALE;

        const float M00 = ca * Sx;
        const float M01 = sa * Sy;
        const float M02 = M00 * dxc + M01 * dyc + Dx;
        const float M10 = -sa * Sx;
        const float M11 = ca * Sy;
        const float M12 = M10 * dxc + M11 * dyc + Dy;

        const float pw  = (float)tid;
        const float ph  = (float)ph_i;
        const float pw1 = pw + 1.0f;
        const float ph1 = ph + 1.0f;

        const float X0 = M00 * pw  + M01 * ph  + M02;
        const float X1 = M00 * pw  + M01 * ph1 + M02;
        const float X2 = M00 * pw1 + M01 * ph  + M02;
        const float X3 = M00 * pw1 + M01 * ph1 + M02;
        const float Y0 = M10 * pw  + M11 * ph  + M12;
        const float Y1 = M10 * pw  + M11 * ph1 + M12;
        const float Y2 = M10 * pw1 + M11 * ph  + M12;
        const float Y3 = M10 * pw1 + M11 * ph1 + M12;

        const float xmn = fminf(fminf(X0, X1), fminf(X2, X3));
        const float xmx = fmaxf(fmaxf(X0, X1), fmaxf(X2, X3));
        const float ymn = fminf(fminf(Y0, Y1), fminf(Y2, Y3));
        const float ymx = fmaxf(fmaxf(Y0, Y1), fmaxf(Y2, Y3));

        const float left   = fmaxf(floorf(xmn + 0.5f), 0.0f);
        const float right  = fminf(floorf(xmx + 0.5f), (float)(WW - 1));
        const float top    = fmaxf(floorf(ymn + 0.5f), 0.0f);
        const float bottom = fminf(floorf(ymx + 0.5f), (float)(HH - 1));

        const float bcx = (left + right) * 0.5f;
        const float bcy = (top + bottom) * 0.5f;

        const float bl = floorf(bcx);
        const float br = ceilf(bcx);
        const float bt = floorf(bcy);
        const float bb = ceilf(bcy);
        const float rx = bcx - bl;
        const float ry = bcy - bt;

        const bool vl = (bl > -1.0f) && (bl < (float)WW);
        const bool vr = (br > -1.0f) && (br < (float)WW);
        const bool vt = (bt > -1.0f) && (bt < (float)HH);
        const bool vb = (bb > -1.0f) && (bb < (float)HH);

        // NOTE: nonzero weights imply ceil==floor+1 for that axis, so the fixed
        // 2x2 patch at (yt..yt+1, xl..xl+1) is exact; zero-weight taps may read
        // the (zeroed) guard band or unrelated data harmlessly.
        float wlt = (1.0f - rx) * (1.0f - ry);
        float wrt = rx * (1.0f - ry);
        float wlb = (1.0f - rx) * ry;
        float wrb = rx * ry;
        if (!(vt && vl)) wlt = 0.0f;
        if (!(vt && vr)) wrt = 0.0f;
        if (!(vb && vl)) wlb = 0.0f;
        if (!(vb && vr)) wrb = 0.0f;

        const int xl = (int)bl;              // raw (unclamped) patch base
        const int yt = (int)bt;

        s_base[tid] = bidx * IMG + (yt * WW + xl) * CC;
        s_w0[tid] = wlt; s_w1[tid] = wrt; s_w2[tid] = wlb; s_w3[tid] = wrb;
    }
    __syncthreads();

    const int bin = tid >> 3;
    const int cg  = tid & 7;

    const float* g = g_nhwc + GUARD;
    const int base = s_base[bin] + cg * 4;
    const float wlt = s_w0[bin], wrt = s_w1[bin], wlb = s_w2[bin], wrb = s_w3[bin];

    const float4 t00 = *reinterpret_cast<const float4*>(g + base);
    const float4 t01 = *reinterpret_cast<const float4*>(g + base + CC);
    const float4 t10 = *reinterpret_cast<const float4*>(g + base + ROWF);
    const float4 t11 = *reinterpret_cast<const float4*>(g + base + ROWF + CC);

    float4 r;
    r.x = wlt * t00.x + wrt * t01.x + wlb * t10.x + wrb * t11.x;
    r.y = wlt * t00.y + wrt * t01.y + wlb * t10.y + wrb * t11.y;
    r.z = wlt * t00.z + wrt * t01.z + wlb * t10.z + wrb * t11.z;
    r.w = wlt * t00.w + wrt * t01.w + wlb * t10.w + wrb * t11.w;

    const int c0 = cg * 4;
    s_r[(c0 + 0) * 65 + bin] = r.x;          // bank-conflict-free (stride 65)
    s_r[(c0 + 1) * 65 + bin] = r.y;
    s_r[(c0 + 2) * 65 + bin] = r.z;
    s_r[(c0 + 3) * 65 + bin] = r.w;
    __syncthreads();

    float* ob = out + (size_t)n * (CC * PH * PW) + ph_i * PW;
#pragma unroll
    for (int i = tid; i < CC * PW; i += 512) {
        const int c = i >> 6;
        const int x = i & 63;
        ob[(size_t)c * (PH * PW) + x] = s_r[c * 65 + x];   // coalesced
    }
}

}  // namespace

extern "C" void kernel_launch(void* const* d_in, const int* in_sizes, int n_in,
                              void* d_out, int out_size) {
    const float* features = (const float*)d_in[0];
    const float* rois     = (const float*)d_in[1];
    float* out            = (float*)d_out;

    const int N = in_sizes[1] / 6;  // 1024

    transpose_kernel<<<BB * HH, 256>>>(features);
    dim3 grid(N, PH);
    rroi_gather_kernel<<<grid, 512>>>(rois, out);
}